// round 2
// baseline (speedup 1.0000x reference)
#include <cuda_runtime.h>
#include <math.h>

#define T_TOK 2048
#define H_DIM 1024
#define I_DIM 512
#define N_EXP 16
#define TOPK  4
#define CAP   2048   // worst-case tokens per expert

#define BM 32
#define BN 128
#define BK 32

// ---------------- device scratch (static globals; no allocation) ----------------
__device__ int   d_cnt[N_EXP];
__device__ int   d_tok[N_EXP * CAP];
__device__ float d_wt [N_EXP * CAP];
__device__ float d_act[(size_t)N_EXP * CAP * I_DIM];   // 64 MB, grouped by expert

// ---------------- init ----------------
__global__ void init_k() {
    if (threadIdx.x < N_EXP) d_cnt[threadIdx.x] = 0;
}

// ---------------- router: logits, softmax-top4-renorm, scatter ----------------
__global__ __launch_bounds__(128) void router_k(const float* __restrict__ x,
                                                const float* __restrict__ gw) {
    __shared__ float xs[H_DIM];
    __shared__ float lg[N_EXP];
    const int t = blockIdx.x;
    const float* xr = x + (size_t)t * H_DIM;
    for (int i = threadIdx.x; i < H_DIM / 4; i += blockDim.x)
        ((float4*)xs)[i] = ((const float4*)xr)[i];
    __syncthreads();

    const int w = threadIdx.x >> 5, lane = threadIdx.x & 31;
    for (int j = 0; j < 4; j++) {
        const int e = w * 4 + j;
        const float* g = gw + (size_t)e * H_DIM;
        float s = 0.f;
        for (int h = lane; h < H_DIM; h += 32) s += xs[h] * g[h];
        #pragma unroll
        for (int o = 16; o; o >>= 1) s += __shfl_xor_sync(0xffffffffu, s, o);
        if (lane == 0) lg[e] = s;
    }
    __syncthreads();

    if (threadIdx.x == 0) {
        int sel[TOPK]; float sl[TOPK];
        unsigned used = 0;
        for (int k = 0; k < TOPK; k++) {
            float best = -1e30f; int bi = 0;
            for (int e = 0; e < N_EXP; e++)
                if (!((used >> e) & 1u) && lg[e] > best) { best = lg[e]; bi = e; }
            used |= 1u << bi; sel[k] = bi; sl[k] = best;
        }
        // renormalized softmax over the 4 selected (global denom cancels)
        float m = sl[0], ex[TOPK], sum = 0.f;
        for (int k = 0; k < TOPK; k++) { ex[k] = expf(sl[k] - m); sum += ex[k]; }
        float inv = 1.f / sum;
        for (int k = 0; k < TOPK; k++) {
            int e = sel[k];
            int pos = atomicAdd(&d_cnt[e], 1);
            d_tok[e * CAP + pos] = t;
            d_wt [e * CAP + pos] = ex[k] * inv;
        }
    }
}

// ---------------- grouped GEMM1: act = silu(X W1^T) * (X W3^T) ----------------
__global__ __launch_bounds__(256) void gemm1_k(const float* __restrict__ x,
                                               const float* __restrict__ w1,
                                               const float* __restrict__ w3) {
    const int e = blockIdx.z;
    const int cnt = d_cnt[e];
    const int m0 = blockIdx.x * BM;
    if (m0 >= cnt) return;
    const int n0 = blockIdx.y * BN;

    __shared__ float Xs [BK][BM + 4];
    __shared__ float W1s[BK][BN + 4];
    __shared__ float W3s[BK][BN + 4];
    __shared__ int toks[BM];

    const int tid = threadIdx.x;
    if (tid < BM) {
        int m = m0 + tid;
        toks[tid] = (m < cnt) ? d_tok[e * CAP + m] : -1;
    }
    __syncthreads();

    const int tm = tid >> 5;      // 0..7  (m group, broadcast within warp)
    const int tn = tid & 31;      // 0..31 (n group)
    const int lm = tid >> 3;      // load row 0..31
    const int lk = (tid & 7) << 2;
    const int mytok = toks[lm];

    const float* w1e = w1 + (size_t)e * I_DIM * H_DIM;
    const float* w3e = w3 + (size_t)e * I_DIM * H_DIM;

    float a1[4][4] = {}, a3[4][4] = {};

    for (int k0 = 0; k0 < H_DIM; k0 += BK) {
        float4 xv = make_float4(0.f, 0.f, 0.f, 0.f);
        if (mytok >= 0)
            xv = *(const float4*)&x[(size_t)mytok * H_DIM + k0 + lk];
        Xs[lk + 0][lm] = xv.x; Xs[lk + 1][lm] = xv.y;
        Xs[lk + 2][lm] = xv.z; Xs[lk + 3][lm] = xv.w;

        #pragma unroll
        for (int v = tid; v < BN * 8; v += 256) {
            int n = v >> 3, kq = (v & 7) << 2;
            size_t off = (size_t)(n0 + n) * H_DIM + k0 + kq;
            float4 a = *(const float4*)&w1e[off];
            W1s[kq + 0][n] = a.x; W1s[kq + 1][n] = a.y;
            W1s[kq + 2][n] = a.z; W1s[kq + 3][n] = a.w;
            float4 b = *(const float4*)&w3e[off];
            W3s[kq + 0][n] = b.x; W3s[kq + 1][n] = b.y;
            W3s[kq + 2][n] = b.z; W3s[kq + 3][n] = b.w;
        }
        __syncthreads();

        #pragma unroll
        for (int k = 0; k < BK; k++) {
            float4 xm = *(float4*)&Xs [k][tm * 4];   // broadcast within warp
            float4 p  = *(float4*)&W1s[k][tn * 4];
            float4 q  = *(float4*)&W3s[k][tn * 4];
            float xa[4] = {xm.x, xm.y, xm.z, xm.w};
            float pa[4] = {p.x, p.y, p.z, p.w};
            float qa[4] = {q.x, q.y, q.z, q.w};
            #pragma unroll
            for (int mi = 0; mi < 4; mi++)
                #pragma unroll
                for (int ni = 0; ni < 4; ni++) {
                    a1[mi][ni] += xa[mi] * pa[ni];
                    a3[mi][ni] += xa[mi] * qa[ni];
                }
        }
        __syncthreads();
    }

    #pragma unroll
    for (int mi = 0; mi < 4; mi++) {
        int m = tm * 4 + mi;
        if (m0 + m >= cnt) continue;
        size_t row = ((size_t)e * CAP + m0 + m) * I_DIM + n0 + tn * 4;
        float4 o;
        { float h = a1[mi][0]; o.x = (h / (1.f + __expf(-h))) * a3[mi][0]; }
        { float h = a1[mi][1]; o.y = (h / (1.f + __expf(-h))) * a3[mi][1]; }
        { float h = a1[mi][2]; o.z = (h / (1.f + __expf(-h))) * a3[mi][2]; }
        { float h = a1[mi][3]; o.w = (h / (1.f + __expf(-h))) * a3[mi][3]; }
        *(float4*)&d_act[row] = o;
    }
}

// ---------------- grouped GEMM2: out += w * (act W2^T) ----------------
__global__ __launch_bounds__(256) void gemm2_k(const float* __restrict__ w2,
                                               float* __restrict__ out) {
    const int e = blockIdx.z;
    const int cnt = d_cnt[e];
    const int m0 = blockIdx.x * BM;
    if (m0 >= cnt) return;
    const int n0 = blockIdx.y * BN;   // over H

    __shared__ float As[BK][BM + 4];
    __shared__ float Ws[BK][BN + 4];
    __shared__ int   toks[BM];
    __shared__ float wts [BM];

    const int tid = threadIdx.x;
    if (tid < BM) {
        int m = m0 + tid;
        toks[tid] = (m < cnt) ? d_tok[e * CAP + m] : -1;
        wts [tid] = (m < cnt) ? d_wt [e * CAP + m] : 0.f;
    }
    __syncthreads();

    const int tm = tid >> 5;
    const int tn = tid & 31;
    const int lm = tid >> 3;
    const int lk = (tid & 7) << 2;
    const bool lv = (m0 + lm < cnt);
    const size_t arow = ((size_t)e * CAP + m0 + lm) * I_DIM;
    const float* w2e = w2 + (size_t)e * H_DIM * I_DIM;

    float acc[4][4] = {};

    for (int k0 = 0; k0 < I_DIM; k0 += BK) {
        float4 av = make_float4(0.f, 0.f, 0.f, 0.f);
        if (lv) av = *(const float4*)&d_act[arow + k0 + lk];
        As[lk + 0][lm] = av.x; As[lk + 1][lm] = av.y;
        As[lk + 2][lm] = av.z; As[lk + 3][lm] = av.w;

        #pragma unroll
        for (int v = tid; v < BN * 8; v += 256) {
            int n = v >> 3, kq = (v & 7) << 2;
            float4 a = *(const float4*)&w2e[(size_t)(n0 + n) * I_DIM + k0 + kq];
            Ws[kq + 0][n] = a.x; Ws[kq + 1][n] = a.y;
            Ws[kq + 2][n] = a.z; Ws[kq + 3][n] = a.w;
        }
        __syncthreads();

        #pragma unroll
        for (int k = 0; k < BK; k++) {
            float4 am = *(float4*)&As[k][tm * 4];
            float4 p  = *(float4*)&Ws[k][tn * 4];
            float aa[4] = {am.x, am.y, am.z, am.w};
            float pa[4] = {p.x, p.y, p.z, p.w};
            #pragma unroll
            for (int mi = 0; mi < 4; mi++)
                #pragma unroll
                for (int ni = 0; ni < 4; ni++)
                    acc[mi][ni] += aa[mi] * pa[ni];
        }
        __syncthreads();
    }

    #pragma unroll
    for (int mi = 0; mi < 4; mi++) {
        int m = tm * 4 + mi;
        if (m0 + m >= cnt) continue;
        int t = toks[m];
        float wv = wts[m];
        float* op = out + (size_t)t * H_DIM + n0 + tn * 4;
        atomicAdd(op + 0, wv * acc[mi][0]);
        atomicAdd(op + 1, wv * acc[mi][1]);
        atomicAdd(op + 2, wv * acc[mi][2]);
        atomicAdd(op + 3, wv * acc[mi][3]);
    }
}

// ---------------- launch ----------------
extern "C" void kernel_launch(void* const* d_in, const int* in_sizes, int n_in,
                              void* d_out, int out_size) {
    const float* x  = (const float*)d_in[0];   // [1,2048,1024]
    const float* gw = (const float*)d_in[1];   // [16,1024]
    const float* w1 = (const float*)d_in[2];   // [16,512,1024]
    const float* w3 = (const float*)d_in[3];   // [16,512,1024]
    const float* w2 = (const float*)d_in[4];   // [16,1024,512]
    float* out = (float*)d_out;

    cudaMemsetAsync(out, 0, (size_t)out_size * sizeof(float), 0);
    init_k<<<1, 32>>>();
    router_k<<<T_TOK, 128>>>(x, gw);
    gemm1_k<<<dim3(CAP / BM, I_DIM / BN, N_EXP), 256>>>(x, w1, w3);
    gemm2_k<<<dim3(CAP / BM, H_DIM / BN, N_EXP), 256>>>(w2, out);
}

// round 6
// speedup vs baseline: 2.8435x; 2.8435x over previous
#include <cuda_runtime.h>
#include <cuda_bf16.h>
#include <math.h>
#include <stdint.h>

#define T_TOK 2048
#define H_DIM 1024
#define I_DIM 512
#define N_EXP 16
#define TOPK  4
#define CAP   2048
#define MT 128          // CTA M tile
#define NT 64           // CTA N tile
#define KC 64           // K chunk (bf16) = 128B rows

// ---------------- device scratch ----------------
__device__ int   d_cnt[N_EXP];
__device__ int   d_tok[N_EXP * CAP];
__device__ int   d_slot[N_EXP * CAP];
__device__ float d_wt [N_EXP * CAP];
__device__ __nv_bfloat16 d_xh[T_TOK * H_DIM];
__device__ __nv_bfloat16 d_xl[T_TOK * H_DIM];
__device__ __nv_bfloat16 d_w1h[N_EXP * I_DIM * H_DIM];
__device__ __nv_bfloat16 d_w1l[N_EXP * I_DIM * H_DIM];
__device__ __nv_bfloat16 d_w3h[N_EXP * I_DIM * H_DIM];
__device__ __nv_bfloat16 d_w3l[N_EXP * I_DIM * H_DIM];
__device__ __nv_bfloat16 d_w2h[N_EXP * H_DIM * I_DIM];
__device__ __nv_bfloat16 d_w2l[N_EXP * H_DIM * I_DIM];
__device__ __nv_bfloat16 d_ah[(size_t)N_EXP * CAP * I_DIM];
__device__ __nv_bfloat16 d_al[(size_t)N_EXP * CAP * I_DIM];
__device__ float d_part[(size_t)T_TOK * TOPK * H_DIM];

// ---------------- helpers ----------------
#define SWZ(o) ((o) ^ (((o) >> 3) & 0x70))

__device__ __forceinline__ uint32_t smem_u32(const void* p) {
    uint32_t a;
    asm("{ .reg .u64 t; cvta.to.shared.u64 t, %1; cvt.u32.u64 %0, t; }" : "=r"(a) : "l"(p));
    return a;
}

#define CP16(sa, ga, sz) \
    asm volatile("cp.async.cg.shared.global [%0], [%1], 16, %2;" \
                 :: "r"(sa), "l"(ga), "r"(sz) : "memory")
#define CP_COMMIT() asm volatile("cp.async.commit_group;" ::: "memory")
#define CP_WAIT(n)  asm volatile("cp.async.wait_group %0;" :: "n"(n) : "memory")

#define LDM4(r0, r1, r2, r3, a) \
    asm volatile("ldmatrix.sync.aligned.m8n8.x4.shared.b16 {%0,%1,%2,%3}, [%4];" \
                 : "=r"(r0), "=r"(r1), "=r"(r2), "=r"(r3) : "r"(a))

#define MMA(d, a, b) \
    asm volatile("mma.sync.aligned.m16n8k16.row.col.f32.bf16.bf16.f32 " \
                 "{%0,%1,%2,%3}, {%4,%5,%6,%7}, {%8,%9}, {%0,%1,%2,%3};" \
                 : "+f"((d)[0]), "+f"((d)[1]), "+f"((d)[2]), "+f"((d)[3]) \
                 : "r"((a)[0]), "r"((a)[1]), "r"((a)[2]), "r"((a)[3]), \
                   "r"((b)[0]), "r"((b)[1]))

// smem layout (dynamic, per buffer)
#define G1_XH  0
#define G1_XL  16384
#define G1_W1H 32768
#define G1_W1L 40960
#define G1_W3H 49152
#define G1_W3L 57344
#define G1_BUF 65536
#define SMEM1 (2 * G1_BUF)
#define G2_AH  0
#define G2_AL  16384
#define G2_WH  32768
#define G2_WL  40960
#define G2_BUF 49152
#define SMEM2 (2 * G2_BUF)

// ---------------- init ----------------
__global__ void init_k() { if (threadIdx.x < N_EXP) d_cnt[threadIdx.x] = 0; }

// ---------------- fp32 -> bf16 hi/lo split ----------------
__device__ __forceinline__ void split_store(__nv_bfloat16* h, __nv_bfloat16* l, int i, float4 v) {
    __nv_bfloat16 h0 = __float2bfloat16(v.x), h1 = __float2bfloat16(v.y);
    __nv_bfloat16 h2 = __float2bfloat16(v.z), h3 = __float2bfloat16(v.w);
    __nv_bfloat16 l0 = __float2bfloat16(v.x - __bfloat162float(h0));
    __nv_bfloat16 l1 = __float2bfloat16(v.y - __bfloat162float(h1));
    __nv_bfloat16 l2 = __float2bfloat16(v.z - __bfloat162float(h2));
    __nv_bfloat16 l3 = __float2bfloat16(v.w - __bfloat162float(h3));
    ((__nv_bfloat162*)h)[2 * i + 0] = __halves2bfloat162(h0, h1);
    ((__nv_bfloat162*)h)[2 * i + 1] = __halves2bfloat162(h2, h3);
    ((__nv_bfloat162*)l)[2 * i + 0] = __halves2bfloat162(l0, l1);
    ((__nv_bfloat162*)l)[2 * i + 1] = __halves2bfloat162(l2, l3);
}

__global__ __launch_bounds__(256) void conv_w_k(const float* __restrict__ w1,
                                                const float* __restrict__ w3,
                                                const float* __restrict__ w2) {
    const int n = N_EXP * I_DIM * H_DIM / 4;
    for (int i = blockIdx.x * blockDim.x + threadIdx.x; i < n; i += gridDim.x * blockDim.x) {
        split_store(d_w1h, d_w1l, i, ((const float4*)w1)[i]);
        split_store(d_w3h, d_w3l, i, ((const float4*)w3)[i]);
        split_store(d_w2h, d_w2l, i, ((const float4*)w2)[i]);
    }
}
__global__ __launch_bounds__(256) void conv_x_k(const float* __restrict__ x) {
    const int n = T_TOK * H_DIM / 4;
    for (int i = blockIdx.x * blockDim.x + threadIdx.x; i < n; i += gridDim.x * blockDim.x)
        split_store(d_xh, d_xl, i, ((const float4*)x)[i]);
}

// ---------------- router ----------------
__global__ __launch_bounds__(128) void router_k(const float* __restrict__ x,
                                                const float* __restrict__ gw) {
    __shared__ float xs[H_DIM];
    __shared__ float lg[N_EXP];
    const int t = blockIdx.x;
    const float* xr = x + (size_t)t * H_DIM;
    for (int i = threadIdx.x; i < H_DIM / 4; i += blockDim.x)
        ((float4*)xs)[i] = ((const float4*)xr)[i];
    __syncthreads();

    const int w = threadIdx.x >> 5, lane = threadIdx.x & 31;
    for (int j = 0; j < 4; j++) {
        const int e = w * 4 + j;
        const float* g = gw + (size_t)e * H_DIM;
        float s = 0.f;
        for (int h = lane; h < H_DIM; h += 32) s += xs[h] * g[h];
        #pragma unroll
        for (int o = 16; o; o >>= 1) s += __shfl_xor_sync(0xffffffffu, s, o);
        if (lane == 0) lg[e] = s;
    }
    __syncthreads();

    if (threadIdx.x == 0) {
        int sel[TOPK]; float sl[TOPK];
        unsigned used = 0;
        for (int k = 0; k < TOPK; k++) {
            float best = -1e30f; int bi = 0;
            for (int e = 0; e < N_EXP; e++)
                if (!((used >> e) & 1u) && lg[e] > best) { best = lg[e]; bi = e; }
            used |= 1u << bi; sel[k] = bi; sl[k] = best;
        }
        float m = sl[0], ex[TOPK], sum = 0.f;
        for (int k = 0; k < TOPK; k++) { ex[k] = expf(sl[k] - m); sum += ex[k]; }
        float inv = 1.f / sum;
        for (int k = 0; k < TOPK; k++) {
            int e = sel[k];
            int pos = atomicAdd(&d_cnt[e], 1);
            d_tok [e * CAP + pos] = t;
            d_slot[e * CAP + pos] = k;
            d_wt  [e * CAP + pos] = ex[k] * inv;
        }
    }
}

// ---------------- gemm1: act = silu(X W1^T) * (X W3^T)  (mma.sync bf16x3) ----------------
__global__ __launch_bounds__(256, 1) void gemm1_t() {
    extern __shared__ char smem[];
    const int e = blockIdx.z, m0 = blockIdx.x * MT, n0 = blockIdx.y * NT;
    const int cnt = d_cnt[e];
    if (m0 >= cnt) return;

    const uint32_t sb = smem_u32(smem);
    const int tid = threadIdx.x, wid = tid >> 5, lid = tid & 31;
    __shared__ int toks[MT];
    if (tid < MT) toks[tid] = (m0 + tid < cnt) ? d_tok[e * CAP + m0 + tid] : -1;
    __syncthreads();

    const __nv_bfloat16* w1he = d_w1h + ((size_t)e * I_DIM + n0) * H_DIM;
    const __nv_bfloat16* w1le = d_w1l + ((size_t)e * I_DIM + n0) * H_DIM;
    const __nv_bfloat16* w3he = d_w3h + ((size_t)e * I_DIM + n0) * H_DIM;
    const __nv_bfloat16* w3le = d_w3l + ((size_t)e * I_DIM + n0) * H_DIM;

    auto load1 = [&](int c, int b) {
        const uint32_t bo = sb + b * G1_BUF;
        const int kb = c * KC;
        for (int v = tid; v < MT * 8; v += 256) {
            const int r = v >> 3, seg = v & 7;
            const uint32_t so = SWZ(r * 128 + seg * 16);
            const int t = toks[r];
            const unsigned p = (t >= 0) ? 16u : 0u;
            const size_t go = (size_t)(t < 0 ? 0 : t) * H_DIM + kb + seg * 8;
            CP16(bo + G1_XH + so, d_xh + go, p);
            CP16(bo + G1_XL + so, d_xl + go, p);
        }
        for (int v = tid; v < NT * 8; v += 256) {
            const int r = v >> 3, seg = v & 7;
            const uint32_t so = SWZ(r * 128 + seg * 16);
            const size_t go = (size_t)r * H_DIM + kb + seg * 8;
            CP16(bo + G1_W1H + so, w1he + go, 16u);
            CP16(bo + G1_W1L + so, w1le + go, 16u);
            CP16(bo + G1_W3H + so, w3he + go, 16u);
            CP16(bo + G1_W3L + so, w3le + go, 16u);
        }
        CP_COMMIT();
    };

    float acc1[2][4][4] = {}, acc3[2][4][4] = {};
    const int wm = wid & 3, wn = wid >> 2;
    const int ar = lid & 15, ac = (lid >> 4) * 8;
    const int bq = lid >> 3, brr = lid & 7;
    const int bn = (bq >> 1) * 8 + brr, bk = (bq & 1) * 8;

    load1(0, 0);
    const int NCH = H_DIM / KC;   // 16
    for (int c = 0; c < NCH; c++) {
        const int b = c & 1;
        if (c + 1 < NCH) { load1(c + 1, (c + 1) & 1); CP_WAIT(1); }
        else CP_WAIT(0);
        __syncthreads();
        const uint32_t bo = sb + b * G1_BUF;

        #pragma unroll
        for (int ks = 0; ks < 4; ks++) {
            const int k = ks * 16;
            uint32_t ah[2][4], al[2][4];
            #pragma unroll
            for (int mi = 0; mi < 2; mi++) {
                const uint32_t off = SWZ((wm * 32 + mi * 16 + ar) * 128 + (k + ac) * 2);
                LDM4(ah[mi][0], ah[mi][1], ah[mi][2], ah[mi][3], bo + G1_XH + off);
                LDM4(al[mi][0], al[mi][1], al[mi][2], al[mi][3], bo + G1_XL + off);
            }
            uint32_t b1h[8], b1l[8], b3h[8], b3l[8];
            #pragma unroll
            for (int nh = 0; nh < 2; nh++) {
                const uint32_t off = SWZ((wn * 32 + nh * 16 + bn) * 128 + (k + bk) * 2);
                LDM4(b1h[4*nh], b1h[4*nh+1], b1h[4*nh+2], b1h[4*nh+3], bo + G1_W1H + off);
                LDM4(b1l[4*nh], b1l[4*nh+1], b1l[4*nh+2], b1l[4*nh+3], bo + G1_W1L + off);
                LDM4(b3h[4*nh], b3h[4*nh+1], b3h[4*nh+2], b3h[4*nh+3], bo + G1_W3H + off);
                LDM4(b3l[4*nh], b3l[4*nh+1], b3l[4*nh+2], b3l[4*nh+3], bo + G1_W3L + off);
            }
            #pragma unroll
            for (int mi = 0; mi < 2; mi++)
                #pragma unroll
                for (int nj = 0; nj < 4; nj++) {
                    MMA(acc1[mi][nj], ah[mi], b1h + 2 * nj);
                    MMA(acc1[mi][nj], ah[mi], b1l + 2 * nj);
                    MMA(acc1[mi][nj], al[mi], b1h + 2 * nj);
                    MMA(acc3[mi][nj], ah[mi], b3h + 2 * nj);
                    MMA(acc3[mi][nj], ah[mi], b3l + 2 * nj);
                    MMA(acc3[mi][nj], al[mi], b3h + 2 * nj);
                }
        }
        __syncthreads();
    }

    // epilogue: silu(h1)*h3, split to bf16 hi/lo
    const int g = lid >> 2, tg = lid & 3;
    #pragma unroll
    for (int mi = 0; mi < 2; mi++)
        #pragma unroll
        for (int sub = 0; sub < 2; sub++) {
            const int m = m0 + wm * 32 + mi * 16 + sub * 8 + g;
            if (m >= cnt) continue;
            const size_t arow = ((size_t)e * CAP + m) * I_DIM + n0 + wn * 32;
            #pragma unroll
            for (int nj = 0; nj < 4; nj++) {
                float h0 = acc1[mi][nj][2*sub],   h1 = acc1[mi][nj][2*sub+1];
                float g0 = acc3[mi][nj][2*sub],   g1 = acc3[mi][nj][2*sub+1];
                float v0 = (h0 / (1.f + expf(-h0))) * g0;
                float v1 = (h1 / (1.f + expf(-h1))) * g1;
                __nv_bfloat16 a0 = __float2bfloat16(v0), a1 = __float2bfloat16(v1);
                __nv_bfloat16 b0 = __float2bfloat16(v0 - __bfloat162float(a0));
                __nv_bfloat16 b1 = __float2bfloat16(v1 - __bfloat162float(a1));
                const size_t idx = arow + nj * 8 + 2 * tg;
                *(__nv_bfloat162*)(d_ah + idx) = __halves2bfloat162(a0, a1);
                *(__nv_bfloat162*)(d_al + idx) = __halves2bfloat162(b0, b1);
            }
        }
}

// ---------------- gemm2: part[t][slot] = w * (act W2^T)  (mma.sync bf16x3) ----------------
__global__ __launch_bounds__(256, 2) void gemm2_t() {
    extern __shared__ char smem[];
    const int e = blockIdx.z, m0 = blockIdx.x * MT, n0 = blockIdx.y * NT;  // n over H
    const int cnt = d_cnt[e];
    if (m0 >= cnt) return;

    const uint32_t sb = smem_u32(smem);
    const int tid = threadIdx.x, wid = tid >> 5, lid = tid & 31;
    __shared__ int   toks[MT];
    __shared__ int   slots[MT];
    __shared__ float wts[MT];
    if (tid < MT) {
        const int m = m0 + tid;
        const bool v = (m < cnt);
        toks [tid] = v ? d_tok [e * CAP + m] : 0;
        slots[tid] = v ? d_slot[e * CAP + m] : 0;
        wts  [tid] = v ? d_wt  [e * CAP + m] : 0.f;
    }
    __syncthreads();

    const __nv_bfloat16* whe = d_w2h + ((size_t)e * H_DIM + n0) * I_DIM;
    const __nv_bfloat16* wle = d_w2l + ((size_t)e * H_DIM + n0) * I_DIM;
    const size_t abase = ((size_t)e * CAP + m0) * I_DIM;

    auto load2 = [&](int c, int b) {
        const uint32_t bo = sb + b * G2_BUF;
        const int kb = c * KC;
        for (int v = tid; v < MT * 8; v += 256) {
            const int r = v >> 3, seg = v & 7;
            const uint32_t so = SWZ(r * 128 + seg * 16);
            const unsigned p = (m0 + r < cnt) ? 16u : 0u;
            const size_t go = abase + (size_t)r * I_DIM + kb + seg * 8;
            CP16(bo + G2_AH + so, d_ah + go, p);
            CP16(bo + G2_AL + so, d_al + go, p);
        }
        for (int v = tid; v < NT * 8; v += 256) {
            const int r = v >> 3, seg = v & 7;
            const uint32_t so = SWZ(r * 128 + seg * 16);
            const size_t go = (size_t)r * I_DIM + kb + seg * 8;
            CP16(bo + G2_WH + so, whe + go, 16u);
            CP16(bo + G2_WL + so, wle + go, 16u);
        }
        CP_COMMIT();
    };

    float acc[2][4][4] = {};
    const int wm = wid & 3, wn = wid >> 2;
    const int ar = lid & 15, ac = (lid >> 4) * 8;
    const int bq = lid >> 3, brr = lid & 7;
    const int bn = (bq >> 1) * 8 + brr, bk = (bq & 1) * 8;

    load2(0, 0);
    const int NCH = I_DIM / KC;   // 8
    for (int c = 0; c < NCH; c++) {
        const int b = c & 1;
        if (c + 1 < NCH) { load2(c + 1, (c + 1) & 1); CP_WAIT(1); }
        else CP_WAIT(0);
        __syncthreads();
        const uint32_t bo = sb + b * G2_BUF;

        #pragma unroll
        for (int ks = 0; ks < 4; ks++) {
            const int k = ks * 16;
            uint32_t ah[2][4], al[2][4];
            #pragma unroll
            for (int mi = 0; mi < 2; mi++) {
                const uint32_t off = SWZ((wm * 32 + mi * 16 + ar) * 128 + (k + ac) * 2);
                LDM4(ah[mi][0], ah[mi][1], ah[mi][2], ah[mi][3], bo + G2_AH + off);
                LDM4(al[mi][0], al[mi][1], al[mi][2], al[mi][3], bo + G2_AL + off);
            }
            uint32_t bh[8], bl[8];
            #pragma unroll
            for (int nh = 0; nh < 2; nh++) {
                const uint32_t off = SWZ((wn * 32 + nh * 16 + bn) * 128 + (k + bk) * 2);
                LDM4(bh[4*nh], bh[4*nh+1], bh[4*nh+2], bh[4*nh+3], bo + G2_WH + off);
                LDM4(bl[4*nh], bl[4*nh+1], bl[4*nh+2], bl[4*nh+3], bo + G2_WL + off);
            }
            #pragma unroll
            for (int mi = 0; mi < 2; mi++)
                #pragma unroll
                for (int nj = 0; nj < 4; nj++) {
                    MMA(acc[mi][nj], ah[mi], bh + 2 * nj);
                    MMA(acc[mi][nj], ah[mi], bl + 2 * nj);
                    MMA(acc[mi][nj], al[mi], bh + 2 * nj);
                }
        }
        __syncthreads();
    }

    const int g = lid >> 2, tg = lid & 3;
    #pragma unroll
    for (int mi = 0; mi < 2; mi++)
        #pragma unroll
        for (int sub = 0; sub < 2; sub++) {
            const int mrow = wm * 32 + mi * 16 + sub * 8 + g;
            if (m0 + mrow >= cnt) continue;
            const int t = toks[mrow], sk = slots[mrow];
            const float wv = wts[mrow];
            const size_t pbase = ((size_t)t * TOPK + sk) * H_DIM + n0 + wn * 32;
            #pragma unroll
            for (int nj = 0; nj < 4; nj++) {
                float2 o;
                o.x = wv * acc[mi][nj][2*sub];
                o.y = wv * acc[mi][nj][2*sub+1];
                *(float2*)(d_part + pbase + nj * 8 + 2 * tg) = o;
            }
        }
}

// ---------------- combine: out[t][h] = sum_k part[t][k][h] ----------------
__global__ __launch_bounds__(256) void combine_k(float* __restrict__ out) {
    const int idx = blockIdx.x * blockDim.x + threadIdx.x;   // over T_TOK*256 float4
    const int t = idx >> 8, c4 = idx & 255;
    const float4* p = (const float4*)d_part + (size_t)t * TOPK * 256 + c4;
    float4 a = p[0], b = p[256], c = p[512], d = p[768];
    float4 o;
    o.x = a.x + b.x + c.x + d.x;
    o.y = a.y + b.y + c.y + d.y;
    o.z = a.z + b.z + c.z + d.z;
    o.w = a.w + b.w + c.w + d.w;
    ((float4*)out)[idx] = o;
}

// ---------------- launch ----------------
extern "C" void kernel_launch(void* const* d_in, const int* in_sizes, int n_in,
                              void* d_out, int out_size) {
    const float* x  = (const float*)d_in[0];
    const float* gw = (const float*)d_in[1];
    const float* w1 = (const float*)d_in[2];
    const float* w3 = (const float*)d_in[3];
    const float* w2 = (const float*)d_in[4];
    float* out = (float*)d_out;

    static int configured = 0;
    cudaFuncSetAttribute(gemm1_t, cudaFuncAttributeMaxDynamicSharedMemorySize, SMEM1);
    cudaFuncSetAttribute(gemm2_t, cudaFuncAttributeMaxDynamicSharedMemorySize, SMEM2);
    (void)configured;

    init_k<<<1, 32>>>();
    conv_w_k<<<2048, 256>>>(w1, w3, w2);
    conv_x_k<<<512, 256>>>(x);
    router_k<<<T_TOK, 128>>>(x, gw);
    gemm1_t<<<dim3(CAP / MT, I_DIM / NT, N_EXP), 256, SMEM1>>>();
    gemm2_t<<<dim3(CAP / MT, H_DIM / NT, N_EXP), 256, SMEM2>>>();
    combine_k<<<T_TOK * 256 / 256, 256>>>(out);
}

// round 8
// speedup vs baseline: 2.9058x; 1.0219x over previous
#include <cuda_runtime.h>
#include <cuda_bf16.h>
#include <math.h>
#include <stdint.h>

#define T_TOK 2048
#define H_DIM 1024
#define I_DIM 512
#define N_EXP 16
#define TOPK  4
#define CAP   2048
#define MT 128
#define KC 64

// ---------------- device scratch ----------------
__device__ int   d_cnt[N_EXP];
__device__ int   d_tok[N_EXP * CAP];
__device__ int   d_slot[N_EXP * CAP];
__device__ float d_wt [N_EXP * CAP];
__device__ __nv_bfloat16 d_xh[T_TOK * H_DIM];
__device__ __nv_bfloat16 d_xl[T_TOK * H_DIM];
__device__ __nv_bfloat16 d_w1h[N_EXP * I_DIM * H_DIM];
__device__ __nv_bfloat16 d_w1l[N_EXP * I_DIM * H_DIM];
__device__ __nv_bfloat16 d_w3h[N_EXP * I_DIM * H_DIM];
__device__ __nv_bfloat16 d_w3l[N_EXP * I_DIM * H_DIM];
__device__ __nv_bfloat16 d_w2h[N_EXP * H_DIM * I_DIM];
__device__ __nv_bfloat16 d_w2l[N_EXP * H_DIM * I_DIM];
__device__ __nv_bfloat16 d_ah[(size_t)N_EXP * CAP * I_DIM];
__device__ __nv_bfloat16 d_al[(size_t)N_EXP * CAP * I_DIM];
__device__ float d_part[(size_t)T_TOK * TOPK * H_DIM];

// ---------------- helpers ----------------
#define SWZ(o) ((o) ^ (((o) >> 3) & 0x70))

__device__ __forceinline__ uint32_t smem_u32(const void* p) {
    uint32_t a;
    asm("{ .reg .u64 t; cvta.to.shared.u64 t, %1; cvt.u32.u64 %0, t; }" : "=r"(a) : "l"(p));
    return a;
}

#define CP16(sa, ga, sz) \
    asm volatile("cp.async.cg.shared.global [%0], [%1], 16, %2;" \
                 :: "r"(sa), "l"(ga), "r"(sz) : "memory")
#define CP_COMMIT() asm volatile("cp.async.commit_group;" ::: "memory")
#define CP_WAIT(n)  asm volatile("cp.async.wait_group %0;" :: "n"(n) : "memory")

#define LDM4(r0, r1, r2, r3, a) \
    asm volatile("ldmatrix.sync.aligned.m8n8.x4.shared.b16 {%0,%1,%2,%3}, [%4];" \
                 : "=r"(r0), "=r"(r1), "=r"(r2), "=r"(r3) : "r"(a))

#define MMA(d, a, b) \
    asm volatile("mma.sync.aligned.m16n8k16.row.col.f32.bf16.bf16.f32 " \
                 "{%0,%1,%2,%3}, {%4,%5,%6,%7}, {%8,%9}, {%0,%1,%2,%3};" \
                 : "+f"((d)[0]), "+f"((d)[1]), "+f"((d)[2]), "+f"((d)[3]) \
                 : "r"((a)[0]), "r"((a)[1]), "r"((a)[2]), "r"((a)[3]), \
                   "r"((b)[0]), "r"((b)[1]))

// smem layouts (per buffer)
#define G1_XH  0
#define G1_XL  16384
#define G1_W1H 32768
#define G1_W1L 40960
#define G1_W3H 49152
#define G1_W3L 57344
#define G1_BUF 65536
#define SMEM1 (2 * G1_BUF)
#define G2_AH  0
#define G2_AL  16384
#define G2_WH  32768
#define G2_WL  49152
#define G2_BUF 65536
#define SMEM2 (2 * G2_BUF)
#define NPAD 68

// ---------------- init ----------------
__global__ void init_k() { if (threadIdx.x < N_EXP) d_cnt[threadIdx.x] = 0; }

// ---------------- fp32 -> bf16 hi/lo split ----------------
__device__ __forceinline__ void split_store(__nv_bfloat16* h, __nv_bfloat16* l, int i, float4 v) {
    __nv_bfloat16 h0 = __float2bfloat16(v.x), h1 = __float2bfloat16(v.y);
    __nv_bfloat16 h2 = __float2bfloat16(v.z), h3 = __float2bfloat16(v.w);
    __nv_bfloat16 l0 = __float2bfloat16(v.x - __bfloat162float(h0));
    __nv_bfloat16 l1 = __float2bfloat16(v.y - __bfloat162float(h1));
    __nv_bfloat16 l2 = __float2bfloat16(v.z - __bfloat162float(h2));
    __nv_bfloat16 l3 = __float2bfloat16(v.w - __bfloat162float(h3));
    ((__nv_bfloat162*)h)[2 * i + 0] = __halves2bfloat162(h0, h1);
    ((__nv_bfloat162*)h)[2 * i + 1] = __halves2bfloat162(h2, h3);
    ((__nv_bfloat162*)l)[2 * i + 0] = __halves2bfloat162(l0, l1);
    ((__nv_bfloat162*)l)[2 * i + 1] = __halves2bfloat162(l2, l3);
}

// ---------------- fused prep: conv_w + conv_x + router ----------------
#define PREP_W_BLOCKS 2048
#define PREP_X_BLOCKS 256
__global__ __launch_bounds__(256) void prep_k(const float* __restrict__ x,
                                              const float* __restrict__ gw,
                                              const float* __restrict__ w1,
                                              const float* __restrict__ w3,
                                              const float* __restrict__ w2) {
    const int b = blockIdx.x;
    const int tid = threadIdx.x;

    if (b < PREP_W_BLOCKS) {
        const int n = N_EXP * I_DIM * H_DIM / 4;
        for (int i = b * 256 + tid; i < n; i += PREP_W_BLOCKS * 256) {
            split_store(d_w1h, d_w1l, i, ((const float4*)w1)[i]);
            split_store(d_w3h, d_w3l, i, ((const float4*)w3)[i]);
            split_store(d_w2h, d_w2l, i, ((const float4*)w2)[i]);
        }
        return;
    }
    if (b < PREP_W_BLOCKS + PREP_X_BLOCKS) {
        const int b2 = b - PREP_W_BLOCKS;
        const int n = T_TOK * H_DIM / 4;
        for (int i = b2 * 256 + tid; i < n; i += PREP_X_BLOCKS * 256)
            split_store(d_xh, d_xl, i, ((const float4*)x)[i]);
        return;
    }

    // router: one token per block, 256 threads (8 warps x 2 experts)
    __shared__ float xs[H_DIM];
    __shared__ float lg[N_EXP];
    const int t = b - (PREP_W_BLOCKS + PREP_X_BLOCKS);
    const float* xr = x + (size_t)t * H_DIM;
    for (int i = tid; i < H_DIM / 4; i += 256)
        ((float4*)xs)[i] = ((const float4*)xr)[i];
    __syncthreads();

    const int w = tid >> 5, lane = tid & 31;
    #pragma unroll
    for (int j = 0; j < 2; j++) {
        const int e = w * 2 + j;
        const float* g = gw + (size_t)e * H_DIM;
        float s = 0.f;
        for (int h = lane; h < H_DIM; h += 32) s += xs[h] * g[h];
        #pragma unroll
        for (int o = 16; o; o >>= 1) s += __shfl_xor_sync(0xffffffffu, s, o);
        if (lane == 0) lg[e] = s;
    }
    __syncthreads();

    if (tid == 0) {
        int sel[TOPK]; float sl[TOPK];
        unsigned used = 0;
        for (int k = 0; k < TOPK; k++) {
            float best = -1e30f; int bi = 0;
            for (int e = 0; e < N_EXP; e++)
                if (!((used >> e) & 1u) && lg[e] > best) { best = lg[e]; bi = e; }
            used |= 1u << bi; sel[k] = bi; sl[k] = best;
        }
        float m = sl[0], ex[TOPK], sum = 0.f;
        for (int k = 0; k < TOPK; k++) { ex[k] = expf(sl[k] - m); sum += ex[k]; }
        float inv = 1.f / sum;
        for (int k = 0; k < TOPK; k++) {
            int e = sel[k];
            int pos = atomicAdd(&d_cnt[e], 1);
            d_tok [e * CAP + pos] = t;
            d_slot[e * CAP + pos] = k;
            d_wt  [e * CAP + pos] = ex[k] * inv;
        }
    }
}

// ---------------- gemm1: act = silu(X W1^T) * (X W3^T) ----------------
// 512 threads: warps 0-7 compute X*W1, warps 8-15 compute X*W3 on the same tiles.
__global__ __launch_bounds__(512, 1) void gemm1_t() {
    extern __shared__ char smem[];
    const int e = blockIdx.z, m0 = blockIdx.x * MT, n0 = blockIdx.y * 64;
    const int cnt = d_cnt[e];
    if (m0 >= cnt) return;

    const uint32_t sb = smem_u32(smem);
    const int tid = threadIdx.x, wid = tid >> 5, lid = tid & 31;
    const int wg = wid >> 3, wl = wid & 7;
    const int wm = wl & 3, wn = wl >> 2;   // 4 x 2 warp grid per group

    __shared__ int toks[MT];
    if (tid < MT) toks[tid] = (m0 + tid < cnt) ? d_tok[e * CAP + m0 + tid] : -1;
    __syncthreads();

    const __nv_bfloat16* w1he = d_w1h + ((size_t)e * I_DIM + n0) * H_DIM;
    const __nv_bfloat16* w1le = d_w1l + ((size_t)e * I_DIM + n0) * H_DIM;
    const __nv_bfloat16* w3he = d_w3h + ((size_t)e * I_DIM + n0) * H_DIM;
    const __nv_bfloat16* w3le = d_w3l + ((size_t)e * I_DIM + n0) * H_DIM;

    auto load1 = [&](int c, int b) {
        const uint32_t bo = sb + b * G1_BUF;
        const int kb = c * KC;
        for (int v = tid; v < MT * 8; v += 512) {
            const int r = v >> 3, seg = v & 7;
            const uint32_t so = SWZ(r * 128 + seg * 16);
            const int t = toks[r];
            const unsigned p = (t >= 0) ? 16u : 0u;
            const size_t go = (size_t)(t < 0 ? 0 : t) * H_DIM + kb + seg * 8;
            CP16(bo + G1_XH + so, d_xh + go, p);
            CP16(bo + G1_XL + so, d_xl + go, p);
        }
        for (int v = tid; v < 64 * 8; v += 512) {
            const int r = v >> 3, seg = v & 7;
            const uint32_t so = SWZ(r * 128 + seg * 16);
            const size_t go = (size_t)r * H_DIM + kb + seg * 8;
            CP16(bo + G1_W1H + so, w1he + go, 16u);
            CP16(bo + G1_W1L + so, w1le + go, 16u);
            CP16(bo + G1_W3H + so, w3he + go, 16u);
            CP16(bo + G1_W3L + so, w3le + go, 16u);
        }
        CP_COMMIT();
    };

    float acc[2][4][4] = {};
    const int ar = lid & 15, ac = (lid >> 4) * 8;
    const int bq = lid >> 3, brr = lid & 7;
    const int bn = (bq >> 1) * 8 + brr, bk = (bq & 1) * 8;
    const uint32_t wBh = wg ? G1_W3H : G1_W1H;
    const uint32_t wBl = wg ? G1_W3L : G1_W1L;

    load1(0, 0);
    const int NCH = H_DIM / KC;   // 16
    for (int c = 0; c < NCH; c++) {
        const int b = c & 1;
        if (c + 1 < NCH) { load1(c + 1, (c + 1) & 1); CP_WAIT(1); }
        else CP_WAIT(0);
        __syncthreads();
        const uint32_t bo = sb + b * G1_BUF;

        #pragma unroll
        for (int ks = 0; ks < 4; ks++) {
            const int k = ks * 16;
            uint32_t ah[2][4], al[2][4];
            #pragma unroll
            for (int mi = 0; mi < 2; mi++) {
                const uint32_t off = SWZ((wm * 32 + mi * 16 + ar) * 128 + (k + ac) * 2);
                LDM4(ah[mi][0], ah[mi][1], ah[mi][2], ah[mi][3], bo + G1_XH + off);
                LDM4(al[mi][0], al[mi][1], al[mi][2], al[mi][3], bo + G1_XL + off);
            }
            #pragma unroll
            for (int nh = 0; nh < 2; nh++) {
                const uint32_t off = SWZ((wn * 32 + nh * 16 + bn) * 128 + (k + bk) * 2);
                uint32_t bh[4], bl[4];
                LDM4(bh[0], bh[1], bh[2], bh[3], bo + wBh + off);
                LDM4(bl[0], bl[1], bl[2], bl[3], bo + wBl + off);
                #pragma unroll
                for (int mi = 0; mi < 2; mi++)
                    #pragma unroll
                    for (int j = 0; j < 2; j++) {
                        const int nj = 2 * nh + j;
                        MMA(acc[mi][nj], ah[mi], bh + 2 * j);
                        MMA(acc[mi][nj], ah[mi], bl + 2 * j);
                        MMA(acc[mi][nj], al[mi], bh + 2 * j);
                    }
            }
        }
        __syncthreads();
    }

    // exchange: w3-group writes its acc to smem, w1-group fuses silu*mul
    float* xch = (float*)smem;
    const int g = lid >> 2, tg = lid & 3;
    if (wg == 1) {
        #pragma unroll
        for (int mi = 0; mi < 2; mi++)
            #pragma unroll
            for (int sub = 0; sub < 2; sub++) {
                const int r = wm * 32 + mi * 16 + sub * 8 + g;
                #pragma unroll
                for (int nj = 0; nj < 4; nj++) {
                    const int cc = wn * 32 + nj * 8 + 2 * tg;
                    *(float2*)&xch[r * NPAD + cc] =
                        make_float2(acc[mi][nj][2 * sub], acc[mi][nj][2 * sub + 1]);
                }
            }
    }
    __syncthreads();
    if (wg == 0) {
        #pragma unroll
        for (int mi = 0; mi < 2; mi++)
            #pragma unroll
            for (int sub = 0; sub < 2; sub++) {
                const int mr = wm * 32 + mi * 16 + sub * 8 + g;
                const int m = m0 + mr;
                if (m >= cnt) continue;
                const size_t arow = ((size_t)e * CAP + m) * I_DIM + n0;
                #pragma unroll
                for (int nj = 0; nj < 4; nj++) {
                    const int cc = wn * 32 + nj * 8 + 2 * tg;
                    float2 g3 = *(float2*)&xch[mr * NPAD + cc];
                    float h0 = acc[mi][nj][2 * sub], h1 = acc[mi][nj][2 * sub + 1];
                    float v0 = (h0 / (1.f + expf(-h0))) * g3.x;
                    float v1 = (h1 / (1.f + expf(-h1))) * g3.y;
                    __nv_bfloat16 a0 = __float2bfloat16(v0), a1 = __float2bfloat16(v1);
                    __nv_bfloat16 b0 = __float2bfloat16(v0 - __bfloat162float(a0));
                    __nv_bfloat16 b1 = __float2bfloat16(v1 - __bfloat162float(a1));
                    *(__nv_bfloat162*)(d_ah + arow + cc) = __halves2bfloat162(a0, a1);
                    *(__nv_bfloat162*)(d_al + arow + cc) = __halves2bfloat162(b0, b1);
                }
            }
    }
}

// ---------------- gemm2: part[t][slot] = w * (act W2^T), CTA 128x128 ----------------
__global__ __launch_bounds__(512, 1) void gemm2_t() {
    extern __shared__ char smem[];
    const int e = blockIdx.z, m0 = blockIdx.x * MT, n0 = blockIdx.y * 128;  // n over H
    const int cnt = d_cnt[e];
    if (m0 >= cnt) return;

    const uint32_t sb = smem_u32(smem);
    const int tid = threadIdx.x, wid = tid >> 5, lid = tid & 31;
    const int wm = wid & 3, wn = wid >> 2;   // 4 x 4 warp grid

    __shared__ int   toks[MT];
    __shared__ int   slots[MT];
    __shared__ float wts[MT];
    if (tid < MT) {
        const int m = m0 + tid;
        const bool v = (m < cnt);
        toks [tid] = v ? d_tok [e * CAP + m] : 0;
        slots[tid] = v ? d_slot[e * CAP + m] : 0;
        wts  [tid] = v ? d_wt  [e * CAP + m] : 0.f;
    }
    __syncthreads();

    const __nv_bfloat16* whe = d_w2h + ((size_t)e * H_DIM + n0) * I_DIM;
    const __nv_bfloat16* wle = d_w2l + ((size_t)e * H_DIM + n0) * I_DIM;
    const size_t abase = ((size_t)e * CAP + m0) * I_DIM;

    auto load2 = [&](int c, int b) {
        const uint32_t bo = sb + b * G2_BUF;
        const int kb = c * KC;
        for (int v = tid; v < MT * 8; v += 512) {
            const int r = v >> 3, seg = v & 7;
            const uint32_t so = SWZ(r * 128 + seg * 16);
            const unsigned p = (m0 + r < cnt) ? 16u : 0u;
            const size_t go = abase + (size_t)r * I_DIM + kb + seg * 8;
            CP16(bo + G2_AH + so, d_ah + go, p);
            CP16(bo + G2_AL + so, d_al + go, p);
        }
        for (int v = tid; v < 128 * 8; v += 512) {
            const int r = v >> 3, seg = v & 7;
            const uint32_t so = SWZ(r * 128 + seg * 16);
            const size_t go = (size_t)r * I_DIM + kb + seg * 8;
            CP16(bo + G2_WH + so, whe + go, 16u);
            CP16(bo + G2_WL + so, wle + go, 16u);
        }
        CP_COMMIT();
    };

    float acc[2][4][4] = {};
    const int ar = lid & 15, ac = (lid >> 4) * 8;
    const int bq = lid >> 3, brr = lid & 7;
    const int bn = (bq >> 1) * 8 + brr, bk = (bq & 1) * 8;

    load2(0, 0);
    const int NCH = I_DIM / KC;   // 8
    for (int c = 0; c < NCH; c++) {
        const int b = c & 1;
        if (c + 1 < NCH) { load2(c + 1, (c + 1) & 1); CP_WAIT(1); }
        else CP_WAIT(0);
        __syncthreads();
        const uint32_t bo = sb + b * G2_BUF;

        #pragma unroll
        for (int ks = 0; ks < 4; ks++) {
            const int k = ks * 16;
            uint32_t ah[2][4], al[2][4];
            #pragma unroll
            for (int mi = 0; mi < 2; mi++) {
                const uint32_t off = SWZ((wm * 32 + mi * 16 + ar) * 128 + (k + ac) * 2);
                LDM4(ah[mi][0], ah[mi][1], ah[mi][2], ah[mi][3], bo + G2_AH + off);
                LDM4(al[mi][0], al[mi][1], al[mi][2], al[mi][3], bo + G2_AL + off);
            }
            #pragma unroll
            for (int nh = 0; nh < 2; nh++) {
                const uint32_t off = SWZ((wn * 32 + nh * 16 + bn) * 128 + (k + bk) * 2);
                uint32_t bh[4], bl[4];
                LDM4(bh[0], bh[1], bh[2], bh[3], bo + G2_WH + off);
                LDM4(bl[0], bl[1], bl[2], bl[3], bo + G2_WL + off);
                #pragma unroll
                for (int mi = 0; mi < 2; mi++)
                    #pragma unroll
                    for (int j = 0; j < 2; j++) {
                        const int nj = 2 * nh + j;
                        MMA(acc[mi][nj], ah[mi], bh + 2 * j);
                        MMA(acc[mi][nj], ah[mi], bl + 2 * j);
                        MMA(acc[mi][nj], al[mi], bh + 2 * j);
                    }
            }
        }
        __syncthreads();
    }

    const int g = lid >> 2, tg = lid & 3;
    #pragma unroll
    for (int mi = 0; mi < 2; mi++)
        #pragma unroll
        for (int sub = 0; sub < 2; sub++) {
            const int mrow = wm * 32 + mi * 16 + sub * 8 + g;
            if (m0 + mrow >= cnt) continue;
            const int t = toks[mrow], sk = slots[mrow];
            const float wv = wts[mrow];
            const size_t pbase = ((size_t)t * TOPK + sk) * H_DIM + n0 + wn * 32;
            #pragma unroll
            for (int nj = 0; nj < 4; nj++) {
                float2 o;
                o.x = wv * acc[mi][nj][2 * sub];
                o.y = wv * acc[mi][nj][2 * sub + 1];
                *(float2*)(d_part + pbase + nj * 8 + 2 * tg) = o;
            }
        }
}

// ---------------- combine ----------------
__global__ __launch_bounds__(256) void combine_k(float* __restrict__ out) {
    const int idx = blockIdx.x * blockDim.x + threadIdx.x;
    const int t = idx >> 8, c4 = idx & 255;
    const float4* p = (const float4*)d_part + (size_t)t * TOPK * 256 + c4;
    float4 a = p[0], b = p[256], c = p[512], d = p[768];
    float4 o;
    o.x = a.x + b.x + c.x + d.x;
    o.y = a.y + b.y + c.y + d.y;
    o.z = a.z + b.z + c.z + d.z;
    o.w = a.w + b.w + c.w + d.w;
    ((float4*)out)[idx] = o;
}

// ---------------- launch ----------------
extern "C" void kernel_launch(void* const* d_in, const int* in_sizes, int n_in,
                              void* d_out, int out_size) {
    const float* x  = (const float*)d_in[0];
    const float* gw = (const float*)d_in[1];
    const float* w1 = (const float*)d_in[2];
    const float* w3 = (const float*)d_in[3];
    const float* w2 = (const float*)d_in[4];
    float* out = (float*)d_out;

    cudaFuncSetAttribute(gemm1_t, cudaFuncAttributeMaxDynamicSharedMemorySize, SMEM1);
    cudaFuncSetAttribute(gemm2_t, cudaFuncAttributeMaxDynamicSharedMemorySize, SMEM2);

    init_k<<<1, 32>>>();
    prep_k<<<PREP_W_BLOCKS + PREP_X_BLOCKS + T_TOK, 256>>>(x, gw, w1, w3, w2);
    gemm1_t<<<dim3(CAP / MT, I_DIM / 64, N_EXP), 512, SMEM1>>>();
    gemm2_t<<<dim3(CAP / MT, H_DIM / 128, N_EXP), 512, SMEM2>>>();
    combine_k<<<T_TOK, 256>>>(out);
}

// round 9
// speedup vs baseline: 3.2048x; 1.1029x over previous
#include <cuda_runtime.h>
#include <cuda_bf16.h>
#include <math.h>
#include <stdint.h>

#define T_TOK 2048
#define H_DIM 1024
#define I_DIM 512
#define N_EXP 16
#define TOPK  4
#define CAP   2048
#define KC 64

// ---------------- device scratch ----------------
__device__ int   d_cnt[N_EXP];
__device__ int   d_tok[N_EXP * CAP];
__device__ int   d_slot[N_EXP * CAP];
__device__ float d_wt [N_EXP * CAP];
__device__ __nv_bfloat16 d_xh[T_TOK * H_DIM];
__device__ __nv_bfloat16 d_xl[T_TOK * H_DIM];
__device__ __nv_bfloat16 d_w1h[N_EXP * I_DIM * H_DIM];
__device__ __nv_bfloat16 d_w1l[N_EXP * I_DIM * H_DIM];
__device__ __nv_bfloat16 d_w3h[N_EXP * I_DIM * H_DIM];
__device__ __nv_bfloat16 d_w3l[N_EXP * I_DIM * H_DIM];
__device__ __nv_bfloat16 d_w2h[N_EXP * H_DIM * I_DIM];
__device__ __nv_bfloat16 d_w2l[N_EXP * H_DIM * I_DIM];
__device__ __nv_bfloat16 d_ah[(size_t)N_EXP * CAP * I_DIM];
__device__ __nv_bfloat16 d_al[(size_t)N_EXP * CAP * I_DIM];
__device__ float d_part[(size_t)T_TOK * TOPK * H_DIM];

// ---------------- helpers ----------------
#define SWZ(o) ((o) ^ (((o) >> 3) & 0x70))

__device__ __forceinline__ uint32_t smem_u32(const void* p) {
    uint32_t a;
    asm("{ .reg .u64 t; cvta.to.shared.u64 t, %1; cvt.u32.u64 %0, t; }" : "=r"(a) : "l"(p));
    return a;
}

#define CP16(sa, ga, sz) \
    asm volatile("cp.async.cg.shared.global [%0], [%1], 16, %2;" \
                 :: "r"(sa), "l"(ga), "r"(sz) : "memory")
#define CP_COMMIT() asm volatile("cp.async.commit_group;" ::: "memory")
#define CP_WAIT(n)  asm volatile("cp.async.wait_group %0;" :: "n"(n) : "memory")

#define LDM4(r0, r1, r2, r3, a) \
    asm volatile("ldmatrix.sync.aligned.m8n8.x4.shared.b16 {%0,%1,%2,%3}, [%4];" \
                 : "=r"(r0), "=r"(r1), "=r"(r2), "=r"(r3) : "r"(a))

#define MMA(d, a, b) \
    asm volatile("mma.sync.aligned.m16n8k16.row.col.f32.bf16.bf16.f32 " \
                 "{%0,%1,%2,%3}, {%4,%5,%6,%7}, {%8,%9}, {%0,%1,%2,%3};" \
                 : "+f"((d)[0]), "+f"((d)[1]), "+f"((d)[2]), "+f"((d)[3]) \
                 : "r"((a)[0]), "r"((a)[1]), "r"((a)[2]), "r"((a)[3]), \
                   "r"((b)[0]), "r"((b)[1]))

// smem layouts (per stage buffer)
// gemm1 (CTA 64x64): XH 8K | XL 8K | W1H 8K | W1L 8K | W3H 8K | W3L 8K = 48K
#define G1_XH  0
#define G1_XL  8192
#define G1_W1H 16384
#define G1_W1L 24576
#define G1_W3H 32768
#define G1_W3L 40960
#define G1_BUF 49152
#define SMEM1 (2 * G1_BUF)
// gemm2 (CTA 128x64): AH 16K | AL 16K | WH 8K | WL 8K = 48K
#define G2_AH  0
#define G2_AL  16384
#define G2_WH  32768
#define G2_WL  40960
#define G2_BUF 49152
#define SMEM2 (2 * G2_BUF)
#define NPAD 68

// ---------------- init ----------------
__global__ void init_k() { if (threadIdx.x < N_EXP) d_cnt[threadIdx.x] = 0; }

// ---------------- fp32 -> bf16 hi/lo split ----------------
__device__ __forceinline__ void split_store(__nv_bfloat16* h, __nv_bfloat16* l, int i, float4 v) {
    __nv_bfloat16 h0 = __float2bfloat16(v.x), h1 = __float2bfloat16(v.y);
    __nv_bfloat16 h2 = __float2bfloat16(v.z), h3 = __float2bfloat16(v.w);
    __nv_bfloat16 l0 = __float2bfloat16(v.x - __bfloat162float(h0));
    __nv_bfloat16 l1 = __float2bfloat16(v.y - __bfloat162float(h1));
    __nv_bfloat16 l2 = __float2bfloat16(v.z - __bfloat162float(h2));
    __nv_bfloat16 l3 = __float2bfloat16(v.w - __bfloat162float(h3));
    ((__nv_bfloat162*)h)[2 * i + 0] = __halves2bfloat162(h0, h1);
    ((__nv_bfloat162*)h)[2 * i + 1] = __halves2bfloat162(h2, h3);
    ((__nv_bfloat162*)l)[2 * i + 0] = __halves2bfloat162(l0, l1);
    ((__nv_bfloat162*)l)[2 * i + 1] = __halves2bfloat162(l2, l3);
}

// ---------------- fused prep: conv_w + conv_x + router ----------------
#define PREP_W_BLOCKS 2048
#define PREP_X_BLOCKS 256
__global__ __launch_bounds__(256) void prep_k(const float* __restrict__ x,
                                              const float* __restrict__ gw,
                                              const float* __restrict__ w1,
                                              const float* __restrict__ w3,
                                              const float* __restrict__ w2) {
    const int b = blockIdx.x;
    const int tid = threadIdx.x;

    if (b < PREP_W_BLOCKS) {
        const int n = N_EXP * I_DIM * H_DIM / 4;
        for (int i = b * 256 + tid; i < n; i += PREP_W_BLOCKS * 256) {
            split_store(d_w1h, d_w1l, i, ((const float4*)w1)[i]);
            split_store(d_w3h, d_w3l, i, ((const float4*)w3)[i]);
            split_store(d_w2h, d_w2l, i, ((const float4*)w2)[i]);
        }
        return;
    }
    if (b < PREP_W_BLOCKS + PREP_X_BLOCKS) {
        const int b2 = b - PREP_W_BLOCKS;
        const int n = T_TOK * H_DIM / 4;
        for (int i = b2 * 256 + tid; i < n; i += PREP_X_BLOCKS * 256)
            split_store(d_xh, d_xl, i, ((const float4*)x)[i]);
        return;
    }

    // router: one token per block
    __shared__ float xs[H_DIM];
    __shared__ float lg[N_EXP];
    const int t = b - (PREP_W_BLOCKS + PREP_X_BLOCKS);
    const float* xr = x + (size_t)t * H_DIM;
    for (int i = tid; i < H_DIM / 4; i += 256)
        ((float4*)xs)[i] = ((const float4*)xr)[i];
    __syncthreads();

    const int w = tid >> 5, lane = tid & 31;
    #pragma unroll
    for (int j = 0; j < 2; j++) {
        const int e = w * 2 + j;
        const float* g = gw + (size_t)e * H_DIM;
        float s = 0.f;
        for (int h = lane; h < H_DIM; h += 32) s += xs[h] * g[h];
        #pragma unroll
        for (int o = 16; o; o >>= 1) s += __shfl_xor_sync(0xffffffffu, s, o);
        if (lane == 0) lg[e] = s;
    }
    __syncthreads();

    if (tid == 0) {
        int sel[TOPK]; float sl[TOPK];
        unsigned used = 0;
        for (int k = 0; k < TOPK; k++) {
            float best = -1e30f; int bi = 0;
            for (int e = 0; e < N_EXP; e++)
                if (!((used >> e) & 1u) && lg[e] > best) { best = lg[e]; bi = e; }
            used |= 1u << bi; sel[k] = bi; sl[k] = best;
        }
        float m = sl[0], ex[TOPK], sum = 0.f;
        for (int k = 0; k < TOPK; k++) { ex[k] = expf(sl[k] - m); sum += ex[k]; }
        float inv = 1.f / sum;
        for (int k = 0; k < TOPK; k++) {
            int e = sel[k];
            int pos = atomicAdd(&d_cnt[e], 1);
            d_tok [e * CAP + pos] = t;
            d_slot[e * CAP + pos] = k;
            d_wt  [e * CAP + pos] = ex[k] * inv;
        }
    }
}

// ---------------- gemm1: act = silu(X W1^T) * (X W3^T) ----------------
// 256 threads, CTA tile 64x64. Warps 0-3 -> X*W1, warps 4-7 -> X*W3 (2x2 each).
__global__ __launch_bounds__(256, 2) void gemm1_t() {
    extern __shared__ char smem[];
    const int e = blockIdx.z, m0 = blockIdx.x * 64, n0 = blockIdx.y * 64;
    const int cnt = d_cnt[e];
    if (m0 >= cnt) return;

    const uint32_t sb = smem_u32(smem);
    const int tid = threadIdx.x, wid = tid >> 5, lid = tid & 31;
    const int wg = wid >> 2, wl = wid & 3;
    const int wm = wl & 1, wn = wl >> 1;   // 2x2 warp grid per group

    __shared__ int toks[64];
    if (tid < 64) toks[tid] = (m0 + tid < cnt) ? d_tok[e * CAP + m0 + tid] : -1;
    __syncthreads();

    const __nv_bfloat16* w1he = d_w1h + ((size_t)e * I_DIM + n0) * H_DIM;
    const __nv_bfloat16* w1le = d_w1l + ((size_t)e * I_DIM + n0) * H_DIM;
    const __nv_bfloat16* w3he = d_w3h + ((size_t)e * I_DIM + n0) * H_DIM;
    const __nv_bfloat16* w3le = d_w3l + ((size_t)e * I_DIM + n0) * H_DIM;

    auto load1 = [&](int c, int b) {
        const uint32_t bo = sb + b * G1_BUF;
        const int kb = c * KC;
        #pragma unroll
        for (int v = tid; v < 64 * 8; v += 256) {
            const int r = v >> 3, seg = v & 7;
            const uint32_t so = SWZ(r * 128 + seg * 16);
            const int t = toks[r];
            const unsigned p = (t >= 0) ? 16u : 0u;
            const size_t go = (size_t)(t < 0 ? 0 : t) * H_DIM + kb + seg * 8;
            CP16(bo + G1_XH + so, d_xh + go, p);
            CP16(bo + G1_XL + so, d_xl + go, p);
        }
        #pragma unroll
        for (int v = tid; v < 64 * 8; v += 256) {
            const int r = v >> 3, seg = v & 7;
            const uint32_t so = SWZ(r * 128 + seg * 16);
            const size_t go = (size_t)r * H_DIM + kb + seg * 8;
            CP16(bo + G1_W1H + so, w1he + go, 16u);
            CP16(bo + G1_W1L + so, w1le + go, 16u);
            CP16(bo + G1_W3H + so, w3he + go, 16u);
            CP16(bo + G1_W3L + so, w3le + go, 16u);
        }
        CP_COMMIT();
    };

    float acc[2][4][4] = {};
    const int ar = lid & 15, ac = (lid >> 4) * 8;
    const int bq = lid >> 3, brr = lid & 7;
    const int bn = (bq >> 1) * 8 + brr, bk = (bq & 1) * 8;
    const uint32_t wBh = wg ? G1_W3H : G1_W1H;
    const uint32_t wBl = wg ? G1_W3L : G1_W1L;

    load1(0, 0);
    const int NCH = H_DIM / KC;   // 16
    for (int c = 0; c < NCH; c++) {
        const int b = c & 1;
        if (c + 1 < NCH) { load1(c + 1, (c + 1) & 1); CP_WAIT(1); }
        else CP_WAIT(0);
        __syncthreads();
        const uint32_t bo = sb + b * G1_BUF;

        #pragma unroll
        for (int ks = 0; ks < 4; ks++) {
            const int k = ks * 16;
            uint32_t ah[2][4], al[2][4];
            #pragma unroll
            for (int mi = 0; mi < 2; mi++) {
                const uint32_t off = SWZ((wm * 32 + mi * 16 + ar) * 128 + (k + ac) * 2);
                LDM4(ah[mi][0], ah[mi][1], ah[mi][2], ah[mi][3], bo + G1_XH + off);
                LDM4(al[mi][0], al[mi][1], al[mi][2], al[mi][3], bo + G1_XL + off);
            }
            #pragma unroll
            for (int nh = 0; nh < 2; nh++) {
                const uint32_t off = SWZ((wn * 32 + nh * 16 + bn) * 128 + (k + bk) * 2);
                uint32_t bh[4], bl[4];
                LDM4(bh[0], bh[1], bh[2], bh[3], bo + wBh + off);
                LDM4(bl[0], bl[1], bl[2], bl[3], bo + wBl + off);
                #pragma unroll
                for (int mi = 0; mi < 2; mi++)
                    #pragma unroll
                    for (int j = 0; j < 2; j++) {
                        const int nj = 2 * nh + j;
                        MMA(acc[mi][nj], ah[mi], bh + 2 * j);
                        MMA(acc[mi][nj], ah[mi], bl + 2 * j);
                        MMA(acc[mi][nj], al[mi], bh + 2 * j);
                    }
            }
        }
        __syncthreads();
    }

    // exchange: w3-group stores acc to smem; w1-group fuses silu*mul and writes act
    float* xch = (float*)smem;   // 64 x NPAD floats = 17.4KB, reuses stage smem
    const int g = lid >> 2, tg = lid & 3;
    if (wg == 1) {
        #pragma unroll
        for (int mi = 0; mi < 2; mi++)
            #pragma unroll
            for (int sub = 0; sub < 2; sub++) {
                const int r = wm * 32 + mi * 16 + sub * 8 + g;
                #pragma unroll
                for (int nj = 0; nj < 4; nj++) {
                    const int cc = wn * 32 + nj * 8 + 2 * tg;
                    *(float2*)&xch[r * NPAD + cc] =
                        make_float2(acc[mi][nj][2 * sub], acc[mi][nj][2 * sub + 1]);
                }
            }
    }
    __syncthreads();
    if (wg == 0) {
        #pragma unroll
        for (int mi = 0; mi < 2; mi++)
            #pragma unroll
            for (int sub = 0; sub < 2; sub++) {
                const int mr = wm * 32 + mi * 16 + sub * 8 + g;
                const int m = m0 + mr;
                if (m >= cnt) continue;
                const size_t arow = ((size_t)e * CAP + m) * I_DIM + n0;
                #pragma unroll
                for (int nj = 0; nj < 4; nj++) {
                    const int cc = wn * 32 + nj * 8 + 2 * tg;
                    float2 g3 = *(float2*)&xch[mr * NPAD + cc];
                    float h0 = acc[mi][nj][2 * sub], h1 = acc[mi][nj][2 * sub + 1];
                    float v0 = (h0 / (1.f + expf(-h0))) * g3.x;
                    float v1 = (h1 / (1.f + expf(-h1))) * g3.y;
                    __nv_bfloat16 a0 = __float2bfloat16(v0), a1 = __float2bfloat16(v1);
                    __nv_bfloat16 b0 = __float2bfloat16(v0 - __bfloat162float(a0));
                    __nv_bfloat16 b1 = __float2bfloat16(v1 - __bfloat162float(a1));
                    *(__nv_bfloat162*)(d_ah + arow + cc) = __halves2bfloat162(a0, a1);
                    *(__nv_bfloat162*)(d_al + arow + cc) = __halves2bfloat162(b0, b1);
                }
            }
    }
}

// ---------------- gemm2: part[t][slot] = w * (act W2^T), CTA 128x64, 256 thr ----------------
__global__ __launch_bounds__(256, 2) void gemm2_t() {
    extern __shared__ char smem[];
    const int e = blockIdx.z, m0 = blockIdx.x * 128, n0 = blockIdx.y * 64;  // n over H
    const int cnt = d_cnt[e];
    if (m0 >= cnt) return;

    const uint32_t sb = smem_u32(smem);
    const int tid = threadIdx.x, wid = tid >> 5, lid = tid & 31;
    const int wm = wid & 3, wn = wid >> 2;   // 4x2 warp grid

    __shared__ int   toks[128];
    __shared__ int   slots[128];
    __shared__ float wts[128];
    if (tid < 128) {
        const int m = m0 + tid;
        const bool v = (m < cnt);
        toks [tid] = v ? d_tok [e * CAP + m] : 0;
        slots[tid] = v ? d_slot[e * CAP + m] : 0;
        wts  [tid] = v ? d_wt  [e * CAP + m] : 0.f;
    }
    __syncthreads();

    const __nv_bfloat16* whe = d_w2h + ((size_t)e * H_DIM + n0) * I_DIM;
    const __nv_bfloat16* wle = d_w2l + ((size_t)e * H_DIM + n0) * I_DIM;
    const size_t abase = ((size_t)e * CAP + m0) * I_DIM;

    auto load2 = [&](int c, int b) {
        const uint32_t bo = sb + b * G2_BUF;
        const int kb = c * KC;
        #pragma unroll
        for (int v = tid; v < 128 * 8; v += 256) {
            const int r = v >> 3, seg = v & 7;
            const uint32_t so = SWZ(r * 128 + seg * 16);
            const unsigned p = (m0 + r < cnt) ? 16u : 0u;
            const size_t go = abase + (size_t)r * I_DIM + kb + seg * 8;
            CP16(bo + G2_AH + so, d_ah + go, p);
            CP16(bo + G2_AL + so, d_al + go, p);
        }
        #pragma unroll
        for (int v = tid; v < 64 * 8; v += 256) {
            const int r = v >> 3, seg = v & 7;
            const uint32_t so = SWZ(r * 128 + seg * 16);
            const size_t go = (size_t)r * I_DIM + kb + seg * 8;
            CP16(bo + G2_WH + so, whe + go, 16u);
            CP16(bo + G2_WL + so, wle + go, 16u);
        }
        CP_COMMIT();
    };

    float acc[2][4][4] = {};
    const int ar = lid & 15, ac = (lid >> 4) * 8;
    const int bq = lid >> 3, brr = lid & 7;
    const int bn = (bq >> 1) * 8 + brr, bk = (bq & 1) * 8;

    load2(0, 0);
    const int NCH = I_DIM / KC;   // 8
    for (int c = 0; c < NCH; c++) {
        const int b = c & 1;
        if (c + 1 < NCH) { load2(c + 1, (c + 1) & 1); CP_WAIT(1); }
        else CP_WAIT(0);
        __syncthreads();
        const uint32_t bo = sb + b * G2_BUF;

        #pragma unroll
        for (int ks = 0; ks < 4; ks++) {
            const int k = ks * 16;
            uint32_t ah[2][4], al[2][4];
            #pragma unroll
            for (int mi = 0; mi < 2; mi++) {
                const uint32_t off = SWZ((wm * 32 + mi * 16 + ar) * 128 + (k + ac) * 2);
                LDM4(ah[mi][0], ah[mi][1], ah[mi][2], ah[mi][3], bo + G2_AH + off);
                LDM4(al[mi][0], al[mi][1], al[mi][2], al[mi][3], bo + G2_AL + off);
            }
            #pragma unroll
            for (int nh = 0; nh < 2; nh++) {
                const uint32_t off = SWZ((wn * 32 + nh * 16 + bn) * 128 + (k + bk) * 2);
                uint32_t bh[4], bl[4];
                LDM4(bh[0], bh[1], bh[2], bh[3], bo + G2_WH + off);
                LDM4(bl[0], bl[1], bl[2], bl[3], bo + G2_WL + off);
                #pragma unroll
                for (int mi = 0; mi < 2; mi++)
                    #pragma unroll
                    for (int j = 0; j < 2; j++) {
                        const int nj = 2 * nh + j;
                        MMA(acc[mi][nj], ah[mi], bh + 2 * j);
                        MMA(acc[mi][nj], ah[mi], bl + 2 * j);
                        MMA(acc[mi][nj], al[mi], bh + 2 * j);
                    }
            }
        }
        __syncthreads();
    }

    const int g = lid >> 2, tg = lid & 3;
    #pragma unroll
    for (int mi = 0; mi < 2; mi++)
        #pragma unroll
        for (int sub = 0; sub < 2; sub++) {
            const int mrow = wm * 32 + mi * 16 + sub * 8 + g;
            if (m0 + mrow >= cnt) continue;
            const int t = toks[mrow], sk = slots[mrow];
            const float wv = wts[mrow];
            const size_t pbase = ((size_t)t * TOPK + sk) * H_DIM + n0 + wn * 32;
            #pragma unroll
            for (int nj = 0; nj < 4; nj++) {
                float2 o;
                o.x = wv * acc[mi][nj][2 * sub];
                o.y = wv * acc[mi][nj][2 * sub + 1];
                *(float2*)(d_part + pbase + nj * 8 + 2 * tg) = o;
            }
        }
}

// ---------------- combine ----------------
__global__ __launch_bounds__(256) void combine_k(float* __restrict__ out) {
    const int idx = blockIdx.x * blockDim.x + threadIdx.x;
    const int t = idx >> 8, c4 = idx & 255;
    const float4* p = (const float4*)d_part + (size_t)t * TOPK * 256 + c4;
    float4 a = p[0], b = p[256], c = p[512], d = p[768];
    float4 o;
    o.x = a.x + b.x + c.x + d.x;
    o.y = a.y + b.y + c.y + d.y;
    o.z = a.z + b.z + c.z + d.z;
    o.w = a.w + b.w + c.w + d.w;
    ((float4*)out)[idx] = o;
}

// ---------------- launch ----------------
extern "C" void kernel_launch(void* const* d_in, const int* in_sizes, int n_in,
                              void* d_out, int out_size) {
    const float* x  = (const float*)d_in[0];
    const float* gw = (const float*)d_in[1];
    const float* w1 = (const float*)d_in[2];
    const float* w3 = (const float*)d_in[3];
    const float* w2 = (const float*)d_in[4];
    float* out = (float*)d_out;

    cudaFuncSetAttribute(gemm1_t, cudaFuncAttributeMaxDynamicSharedMemorySize, SMEM1);
    cudaFuncSetAttribute(gemm2_t, cudaFuncAttributeMaxDynamicSharedMemorySize, SMEM2);

    init_k<<<1, 32>>>();
    prep_k<<<PREP_W_BLOCKS + PREP_X_BLOCKS + T_TOK, 256>>>(x, gw, w1, w3, w2);
    gemm1_t<<<dim3(CAP / 64, I_DIM / 64, N_EXP), 256, SMEM1>>>();
    gemm2_t<<<dim3(CAP / 128, H_DIM / 64, N_EXP), 256, SMEM2>>>();
    combine_k<<<T_TOK, 256>>>(out);
}